// round 3
// baseline (speedup 1.0000x reference)
#include <cuda_runtime.h>
#include <cuda_bf16.h>
#include <stdint.h>
#include <stddef.h>

#define Bq  256
#define Lq  196
#define AFq 2048
#define RSq 512
#define AHq 512
#define IEq 512
#define Mq  (Bq * Lq)            // 50176
#define XK  (IEq + AFq + RSq)    // 3072

// ---------------- device scratch (no allocations allowed) ----------------
__device__ __align__(16) float         g_att_h[Bq * AHq];
__device__ __align__(16) __nv_bfloat16 g_Wctx[AHq * AFq];
__device__ __align__(16) float         g_scores[Bq * Lq];
__device__ __align__(16) float         g_weight[Bq * Lq];
__device__ __align__(16) float         g_x[Bq * XK];          // [xt | att_res | h0]
__device__ __align__(16) float         g_gates[Bq * 4 * RSq];

// ---------------- helpers ----------------
__device__ __forceinline__ uint32_t packbf(float lo, float hi) {
    __nv_bfloat162 h = __floats2bfloat162_rn(lo, hi);
    return *reinterpret_cast<uint32_t*>(&h);
}
__device__ __forceinline__ uint32_t f2tf32(float f) {
    uint32_t r; asm("cvt.rna.tf32.f32 %0, %1;" : "=r"(r) : "f"(f)); return r;
}
__device__ __forceinline__ void mma_bf16(float c[4], const uint32_t a[4], const uint32_t b[2]) {
    asm volatile("mma.sync.aligned.m16n8k16.row.col.f32.bf16.bf16.f32 "
        "{%0,%1,%2,%3}, {%4,%5,%6,%7}, {%8,%9}, {%0,%1,%2,%3};"
        : "+f"(c[0]), "+f"(c[1]), "+f"(c[2]), "+f"(c[3])
        : "r"(a[0]), "r"(a[1]), "r"(a[2]), "r"(a[3]), "r"(b[0]), "r"(b[1]));
}
__device__ __forceinline__ void mma_tf32(float c[4], const uint32_t a[4], const uint32_t b[2]) {
    asm volatile("mma.sync.aligned.m16n8k8.row.col.f32.tf32.tf32.f32 "
        "{%0,%1,%2,%3}, {%4,%5,%6,%7}, {%8,%9}, {%0,%1,%2,%3};"
        : "+f"(c[0]), "+f"(c[1]), "+f"(c[2]), "+f"(c[3])
        : "r"(a[0]), "r"(a[1]), "r"(a[2]), "r"(a[3]), "r"(b[0]), "r"(b[1]));
}

// ---------------- K0: convert W_ctx to bf16; copy xt, h0 into g_x ----------------
__global__ void k0_prep(const float* __restrict__ Wctx, const float* __restrict__ xt,
                        const float* __restrict__ h0) {
    int i = blockIdx.x * blockDim.x + threadIdx.x;
    if (i < AHq * AFq) g_Wctx[i] = __float2bfloat16(Wctx[i]);
    if (i < Bq * IEq) {
        int b = i >> 9, c = i & 511;
        g_x[(size_t)b * XK + c] = xt[i];
    }
    if (i < Bq * RSq) {
        int b = i >> 9, c = i & 511;
        g_x[(size_t)b * XK + IEq + AFq + c] = h0[i];
    }
}

// ---------------- K1: att_h = h0 @ W_h2a^T + b_h2a (fp32, small) ----------------
__global__ void k1_atth(const float* __restrict__ h0, const float* __restrict__ W,
                        const float* __restrict__ bias) {
    __shared__ float As[16][16];
    __shared__ float Bs[16][17];
    int tx = threadIdx.x, ty = threadIdx.y;
    int b  = blockIdx.x * 16 + ty;
    int j  = blockIdx.y * 16 + tx;
    float acc = 0.f;
    for (int k0 = 0; k0 < RSq; k0 += 16) {
        As[ty][tx] = h0[b * RSq + k0 + tx];
        Bs[ty][tx] = W[(blockIdx.y * 16 + ty) * RSq + k0 + tx];
        __syncthreads();
        #pragma unroll
        for (int kk = 0; kk < 16; kk++) acc += As[ty][kk] * Bs[tx][kk];
        __syncthreads();
    }
    g_att_h[b * AHq + j] = acc + bias[j];
}

// ---------------- K2: fused scores (bf16 MMA + tanh + dot W_alpha) ----------------
// Block: 512 threads = 16 warps (2 m-warps x 8 n-warps). Block tile 64 rows x 512 cols.
// Warp tile 32x64 -> 2 x 8 m16n8k16 fragments, K-loop over 2048.
__global__ __launch_bounds__(512, 1)
void k2_scores(const float* __restrict__ att, const float* __restrict__ b_ctx,
               const float* __restrict__ Wal, const float* __restrict__ b_al) {
    int tid = threadIdx.x;
    int warp = tid >> 5, lane = tid & 31;
    int g = lane >> 2, t = lane & 3;
    int wm = warp >> 3, wn = warp & 7;
    int mbase = blockIdx.x * 64 + wm * 32;
    int nbase = wn * 64;

    float acc[2][8][4];
    #pragma unroll
    for (int a = 0; a < 2; a++)
        #pragma unroll
        for (int b = 0; b < 8; b++)
            #pragma unroll
            for (int c = 0; c < 4; c++) acc[a][b][c] = 0.f;

    const float* arow[2][2];
    #pragma unroll
    for (int mf = 0; mf < 2; mf++)
        #pragma unroll
        for (int hh = 0; hh < 2; hh++)
            arow[mf][hh] = att + (size_t)(mbase + 16 * mf + 8 * hh + g) * AFq;

    const __nv_bfloat16* brow[8];
    #pragma unroll
    for (int nf = 0; nf < 8; nf++)
        brow[nf] = g_Wctx + (size_t)(nbase + 8 * nf + g) * AFq;

    for (int k0 = 0; k0 < AFq; k0 += 16) {
        int ka = k0 + 2 * t;
        uint32_t afr[2][4];
        #pragma unroll
        for (int mf = 0; mf < 2; mf++) {
            float2 v00 = *(const float2*)(arow[mf][0] + ka);
            float2 v10 = *(const float2*)(arow[mf][1] + ka);
            float2 v01 = *(const float2*)(arow[mf][0] + ka + 8);
            float2 v11 = *(const float2*)(arow[mf][1] + ka + 8);
            afr[mf][0] = packbf(v00.x, v00.y);
            afr[mf][1] = packbf(v10.x, v10.y);
            afr[mf][2] = packbf(v01.x, v01.y);
            afr[mf][3] = packbf(v11.x, v11.y);
        }
        uint32_t bfr[8][2];
        #pragma unroll
        for (int nf = 0; nf < 8; nf++) {
            bfr[nf][0] = *(const uint32_t*)(brow[nf] + ka);
            bfr[nf][1] = *(const uint32_t*)(brow[nf] + ka + 8);
        }
        #pragma unroll
        for (int mf = 0; mf < 2; mf++)
            #pragma unroll
            for (int nf = 0; nf < 8; nf++)
                mma_bf16(acc[mf][nf], afr[mf], bfr[nf]);
    }

    // Epilogue: val = acc + b_ctx[n] + att_h[b][n]; score += Wal[n]*tanh(val)
    float rsum[2][2];
    #pragma unroll
    for (int mf = 0; mf < 2; mf++) {
        #pragma unroll
        for (int hh = 0; hh < 2; hh++) {
            int m  = mbase + 16 * mf + 8 * hh + g;
            int bb = m / Lq;
            const float* ah = g_att_h + (size_t)bb * AHq;
            float s = 0.f;
            #pragma unroll
            for (int nf = 0; nf < 8; nf++) {
                #pragma unroll
                for (int ci = 0; ci < 2; ci++) {
                    int n = nbase + 8 * nf + 2 * t + ci;
                    float v = acc[mf][nf][hh * 2 + ci] + b_ctx[n] + ah[n];
                    s += Wal[n] * tanhf(v);
                }
            }
            rsum[mf][hh] = s;
        }
    }
    // butterfly reduce over the 4 t-lanes of each group
    #pragma unroll
    for (int off = 1; off < 4; off <<= 1) {
        #pragma unroll
        for (int mf = 0; mf < 2; mf++)
            #pragma unroll
            for (int hh = 0; hh < 2; hh++)
                rsum[mf][hh] += __shfl_xor_sync(0xffffffffu, rsum[mf][hh], off);
    }
    __shared__ float red[64][8];
    if (t == 0) {
        #pragma unroll
        for (int mf = 0; mf < 2; mf++)
            #pragma unroll
            for (int hh = 0; hh < 2; hh++) {
                int rloc = wm * 32 + 16 * mf + 8 * hh + g;
                red[rloc][wn] = rsum[mf][hh];
            }
    }
    __syncthreads();
    if (tid < 64) {
        float s = b_al[0];
        #pragma unroll
        for (int w = 0; w < 8; w++) s += red[tid][w];
        g_scores[blockIdx.x * 64 + tid] = s;
    }
}

// ---------------- K3: softmax over L=196 per batch row ----------------
__global__ void k3_softmax() {
    int b = blockIdx.x;
    int tid = threadIdx.x;  // 256
    __shared__ float sh[256];
    float v = (tid < Lq) ? g_scores[b * Lq + tid] : -1e30f;
    sh[tid] = v; __syncthreads();
    for (int s = 128; s > 0; s >>= 1) {
        if (tid < s) sh[tid] = fmaxf(sh[tid], sh[tid + s]);
        __syncthreads();
    }
    float mx = sh[0]; __syncthreads();
    float e = (tid < Lq) ? __expf(v - mx) : 0.f;
    sh[tid] = e; __syncthreads();
    for (int s = 128; s > 0; s >>= 1) {
        if (tid < s) sh[tid] += sh[tid + s];
        __syncthreads();
    }
    float inv = 1.f / sh[0];
    if (tid < Lq) g_weight[b * Lq + tid] = e * inv;
}

// ---------------- K4: att_res = weight @ att_feats, into g_x middle segment ----------------
__global__ void k4_attres(const float* __restrict__ att) {
    int b  = blockIdx.y;
    int a0 = blockIdx.x * 1024 + threadIdx.x * 4;
    __shared__ float w[Lq];
    for (int i = threadIdx.x; i < Lq; i += blockDim.x) w[i] = g_weight[b * Lq + i];
    __syncthreads();
    float4 acc = make_float4(0.f, 0.f, 0.f, 0.f);
    const float* base = att + (size_t)b * Lq * AFq + a0;
    #pragma unroll 4
    for (int l = 0; l < Lq; l++) {
        float4 v = *(const float4*)(base + (size_t)l * AFq);
        float wl = w[l];
        acc.x += wl * v.x; acc.y += wl * v.y; acc.z += wl * v.z; acc.w += wl * v.w;
    }
    *(float4*)(g_x + (size_t)b * XK + IEq + a0) = acc;
}

// ---------------- K5: gates = x @ W_ih^T + h0 @ W_hh^T  (tf32 MMA) ----------------
// M=256, N=2048, K=3072 (segmented: W_ih for k<2560, W_hh after).
// Block 256 thr = 8 warps (2m x 4n). Block tile 64x128, warp tile 32x32.
__global__ __launch_bounds__(256, 2)
void k5_gates(const float* __restrict__ Wih, const float* __restrict__ Whh) {
    int tid = threadIdx.x;
    int warp = tid >> 5, lane = tid & 31;
    int g = lane >> 2, t = lane & 3;
    int wm = warp >> 2, wn = warp & 3;
    int mbase = blockIdx.x * 64 + wm * 32;
    int nbase = blockIdx.y * 128 + wn * 32;

    float acc[2][4][4];
    #pragma unroll
    for (int a = 0; a < 2; a++)
        #pragma unroll
        for (int b = 0; b < 4; b++)
            #pragma unroll
            for (int c = 0; c < 4; c++) acc[a][b][c] = 0.f;

    const float* arow[2][2];
    #pragma unroll
    for (int mf = 0; mf < 2; mf++)
        #pragma unroll
        for (int hh = 0; hh < 2; hh++)
            arow[mf][hh] = g_x + (size_t)(mbase + 16 * mf + 8 * hh + g) * XK;

    for (int k0 = 0; k0 < XK; k0 += 8) {
        const float* bbase;
        int bstride;
        if (k0 < IEq + AFq) { bbase = Wih + k0;                 bstride = IEq + AFq; }
        else                { bbase = Whh + (k0 - (IEq + AFq)); bstride = RSq;       }

        uint32_t afr[2][4];
        #pragma unroll
        for (int mf = 0; mf < 2; mf++) {
            afr[mf][0] = f2tf32(arow[mf][0][k0 + t]);
            afr[mf][1] = f2tf32(arow[mf][1][k0 + t]);
            afr[mf][2] = f2tf32(arow[mf][0][k0 + t + 4]);
            afr[mf][3] = f2tf32(arow[mf][1][k0 + t + 4]);
        }
        uint32_t bfr[4][2];
        #pragma unroll
        for (int nf = 0; nf < 4; nf++) {
            const float* r = bbase + (size_t)(nbase + 8 * nf + g) * bstride;
            bfr[nf][0] = f2tf32(r[t]);
            bfr[nf][1] = f2tf32(r[t + 4]);
        }
        #pragma unroll
        for (int mf = 0; mf < 2; mf++)
            #pragma unroll
            for (int nf = 0; nf < 4; nf++)
                mma_tf32(acc[mf][nf], afr[mf], bfr[nf]);
    }

    #pragma unroll
    for (int mf = 0; mf < 2; mf++)
        #pragma unroll
        for (int nf = 0; nf < 4; nf++)
            #pragma unroll
            for (int idx = 0; idx < 4; idx++) {
                int hh = idx >> 1, ci = idx & 1;
                int row = mbase + 16 * mf + 8 * hh + g;
                int col = nbase + 8 * nf + 2 * t + ci;
                g_gates[(size_t)row * 2048 + col] = acc[mf][nf][idx];
            }
}

// ---------------- K6: LSTM pointwise + output writes ----------------
__global__ void k6_lstm(const float* __restrict__ c0, float* __restrict__ out, int out_size) {
    int i = blockIdx.x * blockDim.x + threadIdx.x;
    if (i >= Bq * RSq) return;
    int b = i >> 9, r = i & 511;
    const float* gr = g_gates + (size_t)b * 2048;
    float gi = 1.f / (1.f + __expf(-gr[r]));
    float gf = 1.f / (1.f + __expf(-gr[512 + r]));
    float gg = tanhf(gr[1024 + r]);
    float go = 1.f / (1.f + __expf(-gr[1536 + r]));
    float c = gf * c0[i] + gi * gg;
    float h = go * tanhf(c);
    const int N = Bq * RSq;
    out[i] = h;
    if (out_size >= 3 * N) { out[N + i] = h; out[2 * N + i] = c; }
    else if (out_size >= 2 * N) { out[N + i] = c; }
}

// ---------------- launch ----------------
extern "C" void kernel_launch(void* const* d_in, const int* in_sizes, int n_in,
                              void* d_out, int out_size) {
    const float* xt   = (const float*)d_in[0];
    // d_in[1] = fc_feats (unused by reference)
    const float* att  = (const float*)d_in[2];
    const float* h0   = (const float*)d_in[3];
    const float* c0   = (const float*)d_in[4];
    const float* Wctx = (const float*)d_in[5];
    const float* bctx = (const float*)d_in[6];
    const float* Wh2a = (const float*)d_in[7];
    const float* bh2a = (const float*)d_in[8];
    const float* Wal  = (const float*)d_in[9];
    const float* bal  = (const float*)d_in[10];
    const float* Wih  = (const float*)d_in[11];
    const float* Whh  = (const float*)d_in[12];
    float* out = (float*)d_out;

    k0_prep<<<4096, 256>>>(Wctx, xt, h0);
    k1_atth<<<dim3(16, 32), dim3(16, 16)>>>(h0, Wh2a, bh2a);
    k2_scores<<<Mq / 64, 512>>>(att, bctx, Wal, bal);
    k3_softmax<<<Bq, 256>>>();
    k4_attres<<<dim3(2, Bq), 256>>>(att);
    k5_gates<<<dim3(4, 16), 256>>>(Wih, Whh);
    k6_lstm<<<(Bq * RSq + 255) / 256, 256>>>(c0, out, out_size);
}

// round 7
// speedup vs baseline: 1.9111x; 1.9111x over previous
#include <cuda_runtime.h>
#include <cuda_bf16.h>
#include <stdint.h>
#include <stddef.h>

#define Bq  256
#define Lq  196
#define AFq 2048
#define RSq 512
#define AHq 512
#define IEq 512
#define Mq  (Bq * Lq)            // 50176
#define XK  (IEq + AFq + RSq)    // 3072

// ---------------- device scratch (no allocations allowed) ----------------
__device__ __align__(16) float         g_att_h[Bq * AHq];
__device__ __align__(16) __nv_bfloat16 g_Wctx[AHq * AFq];
__device__ __align__(16) float         g_part[4 * Mq];       // per-nblock partial scores
__device__ __align__(16) float         g_weight[Bq * Lq];
__device__ __align__(16) float         g_x[Bq * XK];          // [xt | att_res | h0]
__device__ __align__(16) float         g_gates[Bq * 4 * RSq];

// ---------------- helpers ----------------
__device__ __forceinline__ uint32_t packbf(float lo, float hi) {
    __nv_bfloat162 h = __floats2bfloat162_rn(lo, hi);
    return *reinterpret_cast<uint32_t*>(&h);
}
__device__ __forceinline__ uint32_t f2tf32(float f) {
    uint32_t r; asm("cvt.rna.tf32.f32 %0, %1;" : "=r"(r) : "f"(f)); return r;
}
__device__ __forceinline__ void mma_bf16(float c[4], const uint32_t a[4], const uint32_t b[2]) {
    asm volatile("mma.sync.aligned.m16n8k16.row.col.f32.bf16.bf16.f32 "
        "{%0,%1,%2,%3}, {%4,%5,%6,%7}, {%8,%9}, {%0,%1,%2,%3};"
        : "+f"(c[0]), "+f"(c[1]), "+f"(c[2]), "+f"(c[3])
        : "r"(a[0]), "r"(a[1]), "r"(a[2]), "r"(a[3]), "r"(b[0]), "r"(b[1]));
}
__device__ __forceinline__ void mma_tf32(float c[4], const uint32_t a[4], const uint32_t b[2]) {
    asm volatile("mma.sync.aligned.m16n8k8.row.col.f32.tf32.tf32.f32 "
        "{%0,%1,%2,%3}, {%4,%5,%6,%7}, {%8,%9}, {%0,%1,%2,%3};"
        : "+f"(c[0]), "+f"(c[1]), "+f"(c[2]), "+f"(c[3])
        : "r"(a[0]), "r"(a[1]), "r"(a[2]), "r"(a[3]), "r"(b[0]), "r"(b[1]));
}
__device__ __forceinline__ uint32_t smem_u32(const void* p) {
    return (uint32_t)__cvta_generic_to_shared(p);
}
__device__ __forceinline__ void cp_async16(uint32_t dst, const void* src) {
    asm volatile("cp.async.cg.shared.global [%0], [%1], 16;" :: "r"(dst), "l"(src));
}
__device__ __forceinline__ void cp_commit() {
    asm volatile("cp.async.commit_group;" ::: "memory");
}
__device__ __forceinline__ void cp_wait0() {
    asm volatile("cp.async.wait_group 0;" ::: "memory");
}
__device__ __forceinline__ void ldsm_x4(uint32_t& r0, uint32_t& r1, uint32_t& r2, uint32_t& r3,
                                        uint32_t addr) {
    asm volatile("ldmatrix.sync.aligned.m8n8.x4.shared.b16 {%0,%1,%2,%3}, [%4];"
        : "=r"(r0), "=r"(r1), "=r"(r2), "=r"(r3) : "r"(addr));
}

// ---------------- K0: convert W_ctx to bf16; copy xt, h0 into g_x ----------------
__global__ void k0_prep(const float* __restrict__ Wctx, const float* __restrict__ xt,
                        const float* __restrict__ h0) {
    int i = blockIdx.x * blockDim.x + threadIdx.x;
    if (i < AHq * AFq) g_Wctx[i] = __float2bfloat16(Wctx[i]);
    if (i < Bq * IEq) {
        int b = i >> 9, c = i & 511;
        g_x[(size_t)b * XK + c] = xt[i];
    }
    if (i < Bq * RSq) {
        int b = i >> 9, c = i & 511;
        g_x[(size_t)b * XK + IEq + AFq + c] = h0[i];
    }
}

// ---------------- K1: att_h = h0 @ W_h2a^T + b_h2a ----------------
__global__ void k1_atth(const float* __restrict__ h0, const float* __restrict__ W,
                        const float* __restrict__ bias) {
    __shared__ float As[16][16];
    __shared__ float Bs[16][17];
    int tx = threadIdx.x, ty = threadIdx.y;
    int b  = blockIdx.x * 16 + ty;
    int j  = blockIdx.y * 16 + tx;
    float acc = 0.f;
    for (int k0 = 0; k0 < RSq; k0 += 16) {
        As[ty][tx] = h0[b * RSq + k0 + tx];
        Bs[ty][tx] = W[(blockIdx.y * 16 + ty) * RSq + k0 + tx];
        __syncthreads();
        #pragma unroll
        for (int kk = 0; kk < 16; kk++) acc += As[ty][kk] * Bs[tx][kk];
        __syncthreads();
    }
    g_att_h[b * AHq + j] = acc + bias[j];
}

// ---------------- K2: fused scores — smem-pipelined bf16 mma.sync ----------------
// Grid (392, 4). Block 256 thr = 8 warps (2m x 4n). Block tile 128x128, K-chunk 32.
// smem tiles use 80B row stride (16B-bank conflict-free for ldmatrix).
#define ROWB 80
#define STG_BYTES (128 * ROWB)   // 10240 per tile per stage

__global__ void __launch_bounds__(256, 2)
k2_scores(const float* __restrict__ att, const float* __restrict__ bctx,
          const float* __restrict__ Wal) {
    __shared__ __align__(16) char sA[2][STG_BYTES];
    __shared__ __align__(16) char sB[2][STG_BYTES];
    __shared__ float s_add[2][128];
    __shared__ float s_wal[128];
    __shared__ float s_red[128][4];

    int tid = threadIdx.x;
    int warp = tid >> 5, lane = tid & 31;
    int g = lane >> 2, t = lane & 3;
    int wm = warp >> 2, wn = warp & 3;          // 2 x 4
    int mbase = blockIdx.x * 128;
    int nb    = blockIdx.y;                      // 0..3
    int nbase = nb * 128;
    int b0 = mbase / Lq;

    // epilogue constants
    if (tid < 256) {
        int j = tid >> 7, nc = tid & 127;
        int bb = b0 + j; if (bb >= Bq) bb = Bq - 1;
        s_add[j][nc] = bctx[nbase + nc] + g_att_h[(size_t)bb * AHq + nbase + nc];
    }
    if (tid < 128) s_wal[tid] = Wal[nbase + tid];

    float acc[4][4][4];
    #pragma unroll
    for (int a = 0; a < 4; a++)
        #pragma unroll
        for (int b = 0; b < 4; b++)
            #pragma unroll
            for (int c = 0; c < 4; c++) acc[a][b][c] = 0.f;

    uint32_t aS[2] = { smem_u32(sA[0]), smem_u32(sA[1]) };
    uint32_t bS[2] = { smem_u32(sB[0]), smem_u32(sB[1]) };

    // per-thread staging indices
    // A: 4 x (row=idx>>3 in 0..127, seg=idx&7 -> 4 floats)
    // B: 2 x (row=idx>>2 in 0..127, c=idx&3 -> 16B)
    uint2 regA[4];

    auto ldgA = [&](int kt) {
        int k0 = kt * 32;
        #pragma unroll
        for (int q = 0; q < 4; q++) {
            int idx = q * 256 + tid;
            int row = idx >> 3, seg = idx & 7;
            float4 v = *(const float4*)(att + (size_t)(mbase + row) * AFq + k0 + seg * 4);
            regA[q] = make_uint2(packbf(v.x, v.y), packbf(v.z, v.w));
        }
    };
    auto cpB = [&](int kt, int s) {
        int k0 = kt * 32;
        #pragma unroll
        for (int q = 0; q < 2; q++) {
            int idx = q * 256 + tid;
            int row = idx >> 2, c = idx & 3;
            const void* src = g_Wctx + (size_t)(nbase + row) * AFq + k0 + c * 8;
            cp_async16(bS[s] + row * ROWB + c * 16, src);
        }
        cp_commit();
    };
    auto stsA = [&](int s) {
        #pragma unroll
        for (int q = 0; q < 4; q++) {
            int idx = q * 256 + tid;
            int row = idx >> 3, seg = idx & 7;
            *(uint2*)(sA[s] + row * ROWB + seg * 8) = regA[q];
        }
    };

    // ldmatrix address components (per thread, stage-relative byte offsets)
    // A: row = wm*64 + (lane&15) + mf*16 ; koff = (lane&16 ? 16 : 0) + k16*32
    uint32_t a_off = (uint32_t)(wm * 64 + (lane & 15)) * ROWB + ((lane & 16) ? 16 : 0);
    // B: row = wn*32 + ((lane>>4)&1)*8 + (lane&7) (+16 for 2nd x4); koff = ((lane>>3)&1)*16 + k16*32
    uint32_t b_off = (uint32_t)(wn * 32 + ((lane >> 4) & 1) * 8 + (lane & 7)) * ROWB +
                     ((lane >> 3) & 1) * 16;

    // prologue
    ldgA(0);
    cpB(0, 0);

    for (int kt = 0; kt < AFq / 32; kt++) {
        int s = kt & 1;
        stsA(s);
        cp_wait0();
        __syncthreads();
        if (kt < AFq / 32 - 1) {
            cpB(kt + 1, s ^ 1);
            ldgA(kt + 1);
        }
        #pragma unroll
        for (int k16 = 0; k16 < 2; k16++) {
            uint32_t afr[4][4];
            #pragma unroll
            for (int mf = 0; mf < 4; mf++)
                ldsm_x4(afr[mf][0], afr[mf][1], afr[mf][2], afr[mf][3],
                        aS[s] + a_off + (uint32_t)mf * 16 * ROWB + k16 * 32);
            uint32_t bfr[4][2];
            ldsm_x4(bfr[0][0], bfr[0][1], bfr[1][0], bfr[1][1],
                    bS[s] + b_off + k16 * 32);
            ldsm_x4(bfr[2][0], bfr[2][1], bfr[3][0], bfr[3][1],
                    bS[s] + b_off + 16 * ROWB + k16 * 32);
            #pragma unroll
            for (int mf = 0; mf < 4; mf++)
                #pragma unroll
                for (int nf = 0; nf < 4; nf++)
                    mma_bf16(acc[mf][nf], afr[mf], bfr[nf]);
        }
        __syncthreads();
    }

    // epilogue: partial score over this block's 128 columns
    float rs[4][2];
    #pragma unroll
    for (int mf = 0; mf < 4; mf++) {
        #pragma unroll
        for (int hh = 0; hh < 2; hh++) {
            int row_l = wm * 64 + mf * 16 + hh * 8 + g;
            int m = mbase + row_l;
            int jb = (m / Lq) - b0; if (jb > 1) jb = 1;
            const float* addp = s_add[jb];
            float s = 0.f;
            #pragma unroll
            for (int nf = 0; nf < 4; nf++) {
                #pragma unroll
                for (int ci = 0; ci < 2; ci++) {
                    int nc = wn * 32 + nf * 8 + 2 * t + ci;
                    float v = acc[mf][nf][hh * 2 + ci] + addp[nc];
                    s += s_wal[nc] * tanhf(v);
                }
            }
            rs[mf][hh] = s;
        }
    }
    #pragma unroll
    for (int off = 1; off < 4; off <<= 1)
        #pragma unroll
        for (int mf = 0; mf < 4; mf++)
            #pragma unroll
            for (int hh = 0; hh < 2; hh++)
                rs[mf][hh] += __shfl_xor_sync(0xffffffffu, rs[mf][hh], off);
    if (t == 0) {
        #pragma unroll
        for (int mf = 0; mf < 4; mf++)
            #pragma unroll
            for (int hh = 0; hh < 2; hh++)
                s_red[wm * 64 + mf * 16 + hh * 8 + g][wn] = rs[mf][hh];
    }
    __syncthreads();
    if (tid < 128) {
        float s = s_red[tid][0] + s_red[tid][1] + s_red[tid][2] + s_red[tid][3];
        g_part[(size_t)nb * Mq + mbase + tid] = s;
    }
}

// ---------------- K3: sum partials + softmax over L=196 ----------------
__global__ void k3_softmax(const float* __restrict__ bal) {
    int b = blockIdx.x;
    int tid = threadIdx.x;  // 256
    __shared__ float sh[256];
    float v = -1e30f;
    if (tid < Lq) {
        int m = b * Lq + tid;
        v = g_part[m] + g_part[Mq + m] + g_part[2 * Mq + m] + g_part[3 * Mq + m] + bal[0];
    }
    sh[tid] = v; __syncthreads();
    for (int s = 128; s > 0; s >>= 1) {
        if (tid < s) sh[tid] = fmaxf(sh[tid], sh[tid + s]);
        __syncthreads();
    }
    float mx = sh[0]; __syncthreads();
    float e = (tid < Lq) ? __expf(v - mx) : 0.f;
    sh[tid] = e; __syncthreads();
    for (int s = 128; s > 0; s >>= 1) {
        if (tid < s) sh[tid] += sh[tid + s];
        __syncthreads();
    }
    float inv = 1.f / sh[0];
    if (tid < Lq) g_weight[b * Lq + tid] = e * inv;
}

// ---------------- K4: att_res = weight @ att_feats ----------------
__global__ void k4_attres(const float* __restrict__ att) {
    int b  = blockIdx.y;
    int a0 = blockIdx.x * 1024 + threadIdx.x * 4;
    __shared__ float w[Lq];
    for (int i = threadIdx.x; i < Lq; i += blockDim.x) w[i] = g_weight[b * Lq + i];
    __syncthreads();
    float4 acc = make_float4(0.f, 0.f, 0.f, 0.f);
    const float* base = att + (size_t)b * Lq * AFq + a0;
    #pragma unroll 4
    for (int l = 0; l < Lq; l++) {
        float4 v = *(const float4*)(base + (size_t)l * AFq);
        float wl = w[l];
        acc.x += wl * v.x; acc.y += wl * v.y; acc.z += wl * v.z; acc.w += wl * v.w;
    }
    *(float4*)(g_x + (size_t)b * XK + IEq + a0) = acc;
}

// ---------------- K5: gates = x @ W_ih^T + h0 @ W_hh^T  (tf32 MMA) ----------------
__global__ __launch_bounds__(256, 2)
void k5_gates(const float* __restrict__ Wih, const float* __restrict__ Whh) {
    int tid = threadIdx.x;
    int warp = tid >> 5, lane = tid & 31;
    int g = lane >> 2, t = lane & 3;
    int wm = warp >> 2, wn = warp & 3;
    int mbase = blockIdx.x * 64 + wm * 32;
    int nbase = blockIdx.y * 128 + wn * 32;

    float acc[2][4][4];
    #pragma unroll
    for (int a = 0; a < 2; a++)
        #pragma unroll
        for (int b = 0; b < 4; b++)
            #pragma unroll
            for (int c = 0; c < 4; c++) acc[a][b][c] = 0.f;

    const float* arow[2][2];
    #pragma unroll
    for (int mf = 0; mf < 2; mf++)
        #pragma unroll
        for (int hh = 0; hh < 2; hh++)
            arow[mf][hh] = g_x + (size_t)(mbase + 16 * mf + 8 * hh + g) * XK;

    for (int k0 = 0; k0 < XK; k0 += 8) {
        const float* bbase;
        int bstride;
        if (k0 < IEq + AFq) { bbase = Wih + k0;                 bstride = IEq + AFq; }
        else                { bbase = Whh + (k0 - (IEq + AFq)); bstride = RSq;       }

        uint32_t afr[2][4];
        #pragma unroll
        for (int mf = 0; mf < 2; mf++) {
            afr[mf][0] = f2tf32(arow[mf][0][k0 + t]);
            afr[mf][1] = f2tf32(arow[mf][1][k0 + t]);
            afr[mf][2] = f2tf32(arow[mf][0][k0 + t + 4]);
            afr[mf][3] = f2tf32(arow[mf][1][k0 + t + 4]);
        }
        uint32_t bfr[4][2];
        #pragma unroll
        for (int nf = 0; nf < 4; nf++) {
            const float* r = bbase + (size_t)(nbase + 8 * nf + g) * bstride;
            bfr[nf][0] = f2tf32(r[t]);
            bfr[nf][1] = f2tf32(r[t + 4]);
        }
        #pragma unroll
        for (int mf = 0; mf < 2; mf++)
            #pragma unroll
            for (int nf = 0; nf < 4; nf++)
                mma_tf32(acc[mf][nf], afr[mf], bfr[nf]);
    }

    #pragma unroll
    for (int mf = 0; mf < 2; mf++)
        #pragma unroll
        for (int nf = 0; nf < 4; nf++)
            #pragma unroll
            for (int idx = 0; idx < 4; idx++) {
                int hh = idx >> 1, ci = idx & 1;
                int row = mbase + 16 * mf + 8 * hh + g;
                int col = nbase + 8 * nf + 2 * t + ci;
                g_gates[(size_t)row * 2048 + col] = acc[mf][nf][idx];
            }
}

// ---------------- K6: LSTM pointwise + output writes ----------------
__global__ void k6_lstm(const float* __restrict__ c0, float* __restrict__ out, int out_size) {
    int i = blockIdx.x * blockDim.x + threadIdx.x;
    if (i >= Bq * RSq) return;
    int b = i >> 9, r = i & 511;
    const float* gr = g_gates + (size_t)b * 2048;
    float gi = 1.f / (1.f + __expf(-gr[r]));
    float gf = 1.f / (1.f + __expf(-gr[512 + r]));
    float gg = tanhf(gr[1024 + r]);
    float go = 1.f / (1.f + __expf(-gr[1536 + r]));
    float c = gf * c0[i] + gi * gg;
    float h = go * tanhf(c);
    const int N = Bq * RSq;
    out[i] = h;
    if (out_size >= 3 * N) { out[N + i] = h; out[2 * N + i] = c; }
    else if (out_size >= 2 * N) { out[N + i] = c; }
}

// ---------------- launch ----------------
extern "C" void kernel_launch(void* const* d_in, const int* in_sizes, int n_in,
                              void* d_out, int out_size) {
    const float* xt   = (const float*)d_in[0];
    const float* att  = (const float*)d_in[2];
    const float* h0   = (const float*)d_in[3];
    const float* c0   = (const float*)d_in[4];
    const float* Wctx = (const float*)d_in[5];
    const float* bctx = (const float*)d_in[6];
    const float* Wh2a = (const float*)d_in[7];
    const float* bh2a = (const float*)d_in[8];
    const float* Wal  = (const float*)d_in[9];
    const float* bal  = (const float*)d_in[10];
    const float* Wih  = (const float*)d_in[11];
    const float* Whh  = (const float*)d_in[12];
    float* out = (float*)d_out;

    k0_prep<<<4096, 256>>>(Wctx, xt, h0);
    k1_atth<<<dim3(16, 32), dim3(16, 16)>>>(h0, Wh2a, bh2a);
    k2_scores<<<dim3(Mq / 128, 4), 256>>>(att, bctx, Wal);
    k3_softmax<<<Bq, 256>>>(bal);
    k4_attres<<<dim3(2, Bq), 256>>>(att);
    k5_gates<<<dim3(4, 16), 256>>>(Wih, Whh);
    k6_lstm<<<(Bq * RSq + 255) / 256, 256>>>(c0, out, out_size);
}

// round 8
// speedup vs baseline: 2.1447x; 1.1222x over previous
#include <cuda_runtime.h>
#include <cuda_bf16.h>
#include <stdint.h>
#include <stddef.h>

#define Bq  256
#define Lq  196
#define AFq 2048
#define RSq 512
#define AHq 512
#define IEq 512
#define Mq  (Bq * Lq)            // 50176
#define XK  (IEq + AFq + RSq)    // 3072

// ---------------- device scratch (no allocations allowed) ----------------
__device__ __align__(16) float         g_att_h[Bq * AHq];
__device__ __align__(16) __nv_bfloat16 g_Wctx[AHq * AFq];
__device__ __align__(16) float         g_part[4 * Mq];       // per-nblock partial scores
__device__ __align__(16) float         g_weight[Bq * Lq];
__device__ __align__(16) float         g_x[Bq * XK];          // [xt | att_res | h0]
__device__ __align__(16) float         g_gates[Bq * 4 * RSq];

// ---------------- helpers ----------------
__device__ __forceinline__ uint32_t packbf(float lo, float hi) {
    __nv_bfloat162 h = __floats2bfloat162_rn(lo, hi);
    return *reinterpret_cast<uint32_t*>(&h);
}
__device__ __forceinline__ uint32_t f2tf32(float f) {
    uint32_t r; asm("cvt.rna.tf32.f32 %0, %1;" : "=r"(r) : "f"(f)); return r;
}
__device__ __forceinline__ void mma_bf16(float c[4], const uint32_t a[4], const uint32_t b[2]) {
    asm volatile("mma.sync.aligned.m16n8k16.row.col.f32.bf16.bf16.f32 "
        "{%0,%1,%2,%3}, {%4,%5,%6,%7}, {%8,%9}, {%0,%1,%2,%3};"
        : "+f"(c[0]), "+f"(c[1]), "+f"(c[2]), "+f"(c[3])
        : "r"(a[0]), "r"(a[1]), "r"(a[2]), "r"(a[3]), "r"(b[0]), "r"(b[1]));
}
__device__ __forceinline__ void mma_tf32(float c[4], const uint32_t a[4], const uint32_t b[2]) {
    asm volatile("mma.sync.aligned.m16n8k8.row.col.f32.tf32.tf32.f32 "
        "{%0,%1,%2,%3}, {%4,%5,%6,%7}, {%8,%9}, {%0,%1,%2,%3};"
        : "+f"(c[0]), "+f"(c[1]), "+f"(c[2]), "+f"(c[3])
        : "r"(a[0]), "r"(a[1]), "r"(a[2]), "r"(a[3]), "r"(b[0]), "r"(b[1]));
}
__device__ __forceinline__ uint32_t smem_u32(const void* p) {
    return (uint32_t)__cvta_generic_to_shared(p);
}
__device__ __forceinline__ void cp_async16(uint32_t dst, const void* src) {
    asm volatile("cp.async.cg.shared.global [%0], [%1], 16;" :: "r"(dst), "l"(src));
}
__device__ __forceinline__ void cp_commit() {
    asm volatile("cp.async.commit_group;" ::: "memory");
}
__device__ __forceinline__ void cp_wait1() {
    asm volatile("cp.async.wait_group 1;" ::: "memory");
}
__device__ __forceinline__ void ldsm_x4(uint32_t& r0, uint32_t& r1, uint32_t& r2, uint32_t& r3,
                                        uint32_t addr) {
    asm volatile("ldmatrix.sync.aligned.m8n8.x4.shared.b16 {%0,%1,%2,%3}, [%4];"
        : "=r"(r0), "=r"(r1), "=r"(r2), "=r"(r3) : "r"(addr));
}

// ---------------- K0: convert W_ctx to bf16; copy xt, h0 into g_x ----------------
__global__ void k0_prep(const float* __restrict__ Wctx, const float* __restrict__ xt,
                        const float* __restrict__ h0) {
    int i = blockIdx.x * blockDim.x + threadIdx.x;
    if (i < AHq * AFq) g_Wctx[i] = __float2bfloat16(Wctx[i]);
    if (i < Bq * IEq) {
        int b = i >> 9, c = i & 511;
        g_x[(size_t)b * XK + c] = xt[i];
    }
    if (i < Bq * RSq) {
        int b = i >> 9, c = i & 511;
        g_x[(size_t)b * XK + IEq + AFq + c] = h0[i];
    }
}

// ---------------- K1: att_h = h0 @ W_h2a^T + b_h2a ----------------
__global__ void k1_atth(const float* __restrict__ h0, const float* __restrict__ W,
                        const float* __restrict__ bias) {
    __shared__ float As[16][16];
    __shared__ float Bs[16][17];
    int tx = threadIdx.x, ty = threadIdx.y;
    int b  = blockIdx.x * 16 + ty;
    int j  = blockIdx.y * 16 + tx;
    float acc = 0.f;
    for (int k0 = 0; k0 < RSq; k0 += 16) {
        As[ty][tx] = h0[b * RSq + k0 + tx];
        Bs[ty][tx] = W[(blockIdx.y * 16 + ty) * RSq + k0 + tx];
        __syncthreads();
        #pragma unroll
        for (int kk = 0; kk < 16; kk++) acc += As[ty][kk] * Bs[tx][kk];
        __syncthreads();
    }
    g_att_h[b * AHq + j] = acc + bias[j];
}

// ---------------- nop: aligns ncu capture slot onto k2 ----------------
__global__ void k_nop() {}

// ---------------- K2: fused scores — 3-stage cp.async pipelined bf16 mma.sync ----------------
// Grid (4, 392): nb fastest so the 4 n-siblings of one m-tile co-reside (A L2 reuse).
// Block 256 thr = 8 warps (2m x 4n). Block tile 128x128, K-chunk 32.
#define AROW 160                 // f32 A tile row stride bytes (40 words: bank-clean LDS.64)
#define A_STG (128 * AROW)       // 20480
#define BROW 80                  // bf16 B tile row stride (proven R7)
#define B_STG (128 * BROW)       // 10240
#define OFF_B   (3 * A_STG)                 // 61440
#define OFF_ADD (OFF_B + 3 * B_STG)         // 92160
#define OFF_WAL (OFF_ADD + 2 * 128 * 4)     // 93184
#define OFF_RED (OFF_WAL + 128 * 4)         // 93696
#define K2_SMEM (OFF_RED + 128 * 4 * 4)     // 95744
#define NKT2 (AFq / 32)          // 64

__global__ void __launch_bounds__(256, 2)
k2_scores(const float* __restrict__ att, const float* __restrict__ bctx,
          const float* __restrict__ Wal) {
    extern __shared__ __align__(16) char sm[];
    uint32_t smb = smem_u32(sm);
    float* s_add = (float*)(sm + OFF_ADD);   // [2][128]
    float* s_wal = (float*)(sm + OFF_WAL);   // [128]
    float* s_red = (float*)(sm + OFF_RED);   // [128][4]

    int tid = threadIdx.x;
    int warp = tid >> 5, lane = tid & 31;
    int g = lane >> 2, t = lane & 3;
    int wm = warp >> 2, wn = warp & 3;          // 2 x 4
    int nb    = blockIdx.x;                      // 0..3 (fast dim -> L2 A sharing)
    int mbase = blockIdx.y * 128;
    int nbase = nb * 128;
    int b0 = mbase / Lq;

    // epilogue constants
    {
        int j = tid >> 7, nc = tid & 127;
        int bb = b0 + j; if (bb >= Bq) bb = Bq - 1;
        s_add[j * 128 + nc] = bctx[nbase + nc] + g_att_h[(size_t)bb * AHq + nbase + nc];
        if (tid < 128) s_wal[tid] = Wal[nbase + tid];
    }

    float acc[4][4][4];
    #pragma unroll
    for (int a = 0; a < 4; a++)
        #pragma unroll
        for (int b = 0; b < 4; b++)
            #pragma unroll
            for (int c = 0; c < 4; c++) acc[a][b][c] = 0.f;

    // stage loaders: A fp32 (4 x 16B per thread), B bf16 (2 x 16B per thread)
    auto issue_stage = [&](int kt, int s) {
        int k0 = kt * 32;
        uint32_t aDst = smb + s * A_STG;
        #pragma unroll
        for (int q = 0; q < 4; q++) {
            int idx = q * 256 + tid;
            int row = idx >> 3, seg = idx & 7;
            cp_async16(aDst + row * AROW + seg * 16,
                       att + (size_t)(mbase + row) * AFq + k0 + seg * 4);
        }
        uint32_t bDst = smb + OFF_B + s * B_STG;
        #pragma unroll
        for (int q = 0; q < 2; q++) {
            int idx = q * 256 + tid;
            int row = idx >> 2, c = idx & 3;
            cp_async16(bDst + row * BROW + c * 16,
                       g_Wctx + (size_t)(nbase + row) * AFq + k0 + c * 8);
        }
    };

    // B ldmatrix address (R7-proven mapping)
    uint32_t b_off = (uint32_t)(wn * 32 + ((lane >> 4) & 1) * 8 + (lane & 7)) * BROW +
                     ((lane >> 3) & 1) * 16;
    // A LDS base: row = wm*64 + mf*16 + g, col = k16*16 + 2t (f32)
    uint32_t a_off = (uint32_t)(wm * 64 + g) * AROW + t * 8;

    // prologue: stages 0,1
    issue_stage(0, 0); cp_commit();
    issue_stage(1, 1); cp_commit();

    for (int kt = 0; kt < NKT2; kt++) {
        int s = kt % 3;
        cp_wait1();
        __syncthreads();
        if (kt + 2 < NKT2) issue_stage(kt + 2, (kt + 2) % 3);
        cp_commit();

        uint32_t aBase = smb + s * A_STG + a_off;
        uint32_t bBase = smb + OFF_B + s * B_STG + b_off;
        #pragma unroll
        for (int k16 = 0; k16 < 2; k16++) {
            uint32_t bfr[4][2];
            ldsm_x4(bfr[0][0], bfr[0][1], bfr[1][0], bfr[1][1], bBase + k16 * 32);
            ldsm_x4(bfr[2][0], bfr[2][1], bfr[3][0], bfr[3][1], bBase + 16 * BROW + k16 * 32);
            #pragma unroll
            for (int mf = 0; mf < 4; mf++) {
                uint32_t ab = aBase + (uint32_t)mf * 16 * AROW + k16 * 64;
                float2 v00 = *(const float2*)(sm + (ab - smb));
                float2 v10 = *(const float2*)(sm + (ab - smb) + 8 * AROW);
                float2 v01 = *(const float2*)(sm + (ab - smb) + 32);
                float2 v11 = *(const float2*)(sm + (ab - smb) + 8 * AROW + 32);
                uint32_t afr[4] = { packbf(v00.x, v00.y), packbf(v10.x, v10.y),
                                    packbf(v01.x, v01.y), packbf(v11.x, v11.y) };
                #pragma unroll
                for (int nf = 0; nf < 4; nf++)
                    mma_bf16(acc[mf][nf], afr, bfr[nf]);
            }
        }
        __syncthreads();
    }

    // epilogue: partial score over this block's 128 columns
    float rs[4][2];
    #pragma unroll
    for (int mf = 0; mf < 4; mf++) {
        #pragma unroll
        for (int hh = 0; hh < 2; hh++) {
            int row_l = wm * 64 + mf * 16 + hh * 8 + g;
            int m = mbase + row_l;
            int jb = (m / Lq) - b0; if (jb > 1) jb = 1;
            const float* addp = s_add + jb * 128;
            float s = 0.f;
            #pragma unroll
            for (int nf = 0; nf < 4; nf++) {
                #pragma unroll
                for (int ci = 0; ci < 2; ci++) {
                    int nc = wn * 32 + nf * 8 + 2 * t + ci;
                    float v = acc[mf][nf][hh * 2 + ci] + addp[nc];
                    s += s_wal[nc] * tanhf(v);
                }
            }
            rs[mf][hh] = s;
        }
    }
    #pragma unroll
    for (int off = 1; off < 4; off <<= 1)
        #pragma unroll
        for (int mf = 0; mf < 4; mf++)
            #pragma unroll
            for (int hh = 0; hh < 2; hh++)
                rs[mf][hh] += __shfl_xor_sync(0xffffffffu, rs[mf][hh], off);
    if (t == 0) {
        #pragma unroll
        for (int mf = 0; mf < 4; mf++)
            #pragma unroll
            for (int hh = 0; hh < 2; hh++)
                s_red[(wm * 64 + mf * 16 + hh * 8 + g) * 4 + wn] = rs[mf][hh];
    }
    __syncthreads();
    if (tid < 128) {
        float s = s_red[tid * 4] + s_red[tid * 4 + 1] + s_red[tid * 4 + 2] + s_red[tid * 4 + 3];
        g_part[(size_t)nb * Mq + mbase + tid] = s;
    }
}

// ---------------- K3: sum partials + softmax over L=196 ----------------
__global__ void k3_softmax(const float* __restrict__ bal) {
    int b = blockIdx.x;
    int tid = threadIdx.x;  // 256
    __shared__ float sh[256];
    float v = -1e30f;
    if (tid < Lq) {
        int m = b * Lq + tid;
        v = g_part[m] + g_part[Mq + m] + g_part[2 * Mq + m] + g_part[3 * Mq + m] + bal[0];
    }
    sh[tid] = v; __syncthreads();
    for (int s = 128; s > 0; s >>= 1) {
        if (tid < s) sh[tid] = fmaxf(sh[tid], sh[tid + s]);
        __syncthreads();
    }
    float mx = sh[0]; __syncthreads();
    float e = (tid < Lq) ? __expf(v - mx) : 0.f;
    sh[tid] = e; __syncthreads();
    for (int s = 128; s > 0; s >>= 1) {
        if (tid < s) sh[tid] += sh[tid + s];
        __syncthreads();
    }
    float inv = 1.f / sh[0];
    if (tid < Lq) g_weight[b * Lq + tid] = e * inv;
}

// ---------------- K4: att_res = weight @ att_feats ----------------
__global__ void k4_attres(const float* __restrict__ att) {
    int b  = blockIdx.y;
    int a0 = blockIdx.x * 1024 + threadIdx.x * 4;
    __shared__ float w[Lq];
    for (int i = threadIdx.x; i < Lq; i += blockDim.x) w[i] = g_weight[b * Lq + i];
    __syncthreads();
    float4 acc = make_float4(0.f, 0.f, 0.f, 0.f);
    const float* base = att + (size_t)b * Lq * AFq + a0;
    #pragma unroll 4
    for (int l = 0; l < Lq; l++) {
        float4 v = *(const float4*)(base + (size_t)l * AFq);
        float wl = w[l];
        acc.x += wl * v.x; acc.y += wl * v.y; acc.z += wl * v.z; acc.w += wl * v.w;
    }
    *(float4*)(g_x + (size_t)b * XK + IEq + a0) = acc;
}

// ---------------- K5: gates = x @ W_ih^T + h0 @ W_hh^T  (tf32 MMA) ----------------
__global__ __launch_bounds__(256, 2)
void k5_gates(const float* __restrict__ Wih, const float* __restrict__ Whh) {
    int tid = threadIdx.x;
    int warp = tid >> 5, lane = tid & 31;
    int g = lane >> 2, t = lane & 3;
    int wm = warp >> 2, wn = warp & 3;
    int mbase = blockIdx.x * 64 + wm * 32;
    int nbase = blockIdx.y * 128 + wn * 32;

    float acc[2][4][4];
    #pragma unroll
    for (int a = 0; a < 2; a++)
        #pragma unroll
        for (int b = 0; b < 4; b++)
            #pragma unroll
            for (int c = 0; c < 4; c++) acc[a][b][c] = 0.f;

    const float* arow[2][2];
    #pragma unroll
    for (int mf = 0; mf < 2; mf++)
        #pragma unroll
        for (int hh = 0; hh < 2; hh++)
            arow[mf][hh] = g_x + (size_t)(mbase + 16 * mf + 8 * hh + g) * XK;

    for (int k0 = 0; k0 < XK; k0 += 8) {
        const float* bbase;
        int bstride;
        if (k0 < IEq + AFq) { bbase = Wih + k0;                 bstride = IEq + AFq; }
        else                { bbase = Whh + (k0 - (IEq + AFq)); bstride = RSq;       }

        uint32_t afr[2][4];
        #pragma unroll
        for (int mf = 0; mf < 2; mf++) {
            afr[mf][0] = f2tf32(arow[mf][0][k0 + t]);
            afr[mf][1] = f2tf32(arow[mf][1][k0 + t]);
            afr[mf][2] = f2tf32(arow[mf][0][k0 + t + 4]);
            afr[mf][3] = f2tf32(arow[mf][1][k0 + t + 4]);
        }
        uint32_t bfr[4][2];
        #pragma unroll
        for (int nf = 0; nf < 4; nf++) {
            const float* r = bbase + (size_t)(nbase + 8 * nf + g) * bstride;
            bfr[nf][0] = f2tf32(r[t]);
            bfr[nf][1] = f2tf32(r[t + 4]);
        }
        #pragma unroll
        for (int mf = 0; mf < 2; mf++)
            #pragma unroll
            for (int nf = 0; nf < 4; nf++)
                mma_tf32(acc[mf][nf], afr[mf], bfr[nf]);
    }

    #pragma unroll
    for (int mf = 0; mf < 2; mf++)
        #pragma unroll
        for (int nf = 0; nf < 4; nf++)
            #pragma unroll
            for (int idx = 0; idx < 4; idx++) {
                int hh = idx >> 1, ci = idx & 1;
                int row = mbase + 16 * mf + 8 * hh + g;
                int col = nbase + 8 * nf + 2 * t + ci;
                g_gates[(size_t)row * 2048 + col] = acc[mf][nf][idx];
            }
}

// ---------------- K6: LSTM pointwise + output writes ----------------
__global__ void k6_lstm(const float* __restrict__ c0, float* __restrict__ out, int out_size) {
    int i = blockIdx.x * blockDim.x + threadIdx.x;
    if (i >= Bq * RSq) return;
    int b = i >> 9, r = i & 511;
    const float* gr = g_gates + (size_t)b * 2048;
    float gi = 1.f / (1.f + __expf(-gr[r]));
    float gf = 1.f / (1.f + __expf(-gr[512 + r]));
    float gg = tanhf(gr[1024 + r]);
    float go = 1.f / (1.f + __expf(-gr[1536 + r]));
    float c = gf * c0[i] + gi * gg;
    float h = go * tanhf(c);
    const int N = Bq * RSq;
    out[i] = h;
    if (out_size >= 3 * N) { out[N + i] = h; out[2 * N + i] = c; }
    else if (out_size >= 2 * N) { out[N + i] = c; }
}

// ---------------- launch ----------------
extern "C" void kernel_launch(void* const* d_in, const int* in_sizes, int n_in,
                              void* d_out, int out_size) {
    const float* xt   = (const float*)d_in[0];
    const float* att  = (const float*)d_in[2];
    const float* h0   = (const float*)d_in[3];
    const float* c0   = (const float*)d_in[4];
    const float* Wctx = (const float*)d_in[5];
    const float* bctx = (const float*)d_in[6];
    const float* Wh2a = (const float*)d_in[7];
    const float* bh2a = (const float*)d_in[8];
    const float* Wal  = (const float*)d_in[9];
    const float* bal  = (const float*)d_in[10];
    const float* Wih  = (const float*)d_in[11];
    const float* Whh  = (const float*)d_in[12];
    float* out = (float*)d_out;

    static int smem_set = 0;
    if (!smem_set) {
        cudaFuncSetAttribute(k2_scores, cudaFuncAttributeMaxDynamicSharedMemorySize, K2_SMEM);
        smem_set = 1;
    }

    k0_prep<<<4096, 256>>>(Wctx, xt, h0);
    k1_atth<<<dim3(16, 32), dim3(16, 16)>>>(h0, Wh2a, bh2a);
    k_nop<<<1, 32>>>();
    k2_scores<<<dim3(4, Mq / 128), 256, K2_SMEM>>>(att, bctx, Wal);
    k3_softmax<<<Bq, 256>>>(bal);
    k4_attres<<<dim3(2, Bq), 256>>>(att);
    k5_gates<<<dim3(4, 16), 256>>>(Wih, Whh);
    k6_lstm<<<(Bq * RSq + 255) / 256, 256>>>(c0, out, out_size);
}

// round 9
// speedup vs baseline: 2.6237x; 1.2234x over previous
#include <cuda_runtime.h>
#include <cuda_bf16.h>
#include <stdint.h>
#include <stddef.h>

#define Bq  256
#define Lq  196
#define AFq 2048
#define RSq 512
#define AHq 512
#define IEq 512
#define Mq  (Bq * Lq)            // 50176
#define XK  (IEq + AFq + RSq)    // 3072
#define GSEG (Bq * 4 * RSq)      // 524288 (one split-K partial)

// ---------------- device scratch (no allocations allowed) ----------------
__device__ __align__(16) float         g_att_h[Bq * AHq];
__device__ __align__(16) __nv_bfloat16 g_Wctx[AHq * AFq];
__device__ __align__(16) float         g_part[4 * Mq];       // per-nblock partial scores
__device__ __align__(16) float         g_weight[Bq * Lq];
__device__ __align__(16) float         g_x[Bq * XK];          // [xt | att_res | h0] (tf32-rounded)
__device__ __align__(16) float         g_Wg[4 * RSq * XK];    // [Wih | Whh] concat, tf32-rounded
__device__ __align__(16) float         g_gpart[3 * GSEG];     // split-K gate partials

// ---------------- helpers ----------------
__device__ __forceinline__ uint32_t packbf(float lo, float hi) {
    __nv_bfloat162 h = __floats2bfloat162_rn(lo, hi);
    return *reinterpret_cast<uint32_t*>(&h);
}
__device__ __forceinline__ uint32_t f2tf32(float f) {
    uint32_t r; asm("cvt.rna.tf32.f32 %0, %1;" : "=r"(r) : "f"(f)); return r;
}
__device__ __forceinline__ void mma_bf16(float c[4], const uint32_t a[4], const uint32_t b[2]) {
    asm volatile("mma.sync.aligned.m16n8k16.row.col.f32.bf16.bf16.f32 "
        "{%0,%1,%2,%3}, {%4,%5,%6,%7}, {%8,%9}, {%0,%1,%2,%3};"
        : "+f"(c[0]), "+f"(c[1]), "+f"(c[2]), "+f"(c[3])
        : "r"(a[0]), "r"(a[1]), "r"(a[2]), "r"(a[3]), "r"(b[0]), "r"(b[1]));
}
__device__ __forceinline__ void mma_tf32(float c[4], const uint32_t a[4], const uint32_t b[2]) {
    asm volatile("mma.sync.aligned.m16n8k8.row.col.f32.tf32.tf32.f32 "
        "{%0,%1,%2,%3}, {%4,%5,%6,%7}, {%8,%9}, {%0,%1,%2,%3};"
        : "+f"(c[0]), "+f"(c[1]), "+f"(c[2]), "+f"(c[3])
        : "r"(a[0]), "r"(a[1]), "r"(a[2]), "r"(a[3]), "r"(b[0]), "r"(b[1]));
}
__device__ __forceinline__ uint32_t smem_u32(const void* p) {
    return (uint32_t)__cvta_generic_to_shared(p);
}
__device__ __forceinline__ void cp_async16(uint32_t dst, const void* src) {
    asm volatile("cp.async.cg.shared.global [%0], [%1], 16;" :: "r"(dst), "l"(src));
}
__device__ __forceinline__ void cp_commit() {
    asm volatile("cp.async.commit_group;" ::: "memory");
}
__device__ __forceinline__ void cp_wait1() {
    asm volatile("cp.async.wait_group 1;" ::: "memory");
}
__device__ __forceinline__ void ldsm_x4(uint32_t& r0, uint32_t& r1, uint32_t& r2, uint32_t& r3,
                                        uint32_t addr) {
    asm volatile("ldmatrix.sync.aligned.m8n8.x4.shared.b16 {%0,%1,%2,%3}, [%4];"
        : "=r"(r0), "=r"(r1), "=r"(r2), "=r"(r3) : "r"(addr));
}

// ---------------- K0: W_ctx->bf16; xt,h0 -> g_x (tf32-rounded) ----------------
__global__ void k0_prep(const float* __restrict__ Wctx, const float* __restrict__ xt,
                        const float* __restrict__ h0) {
    int i = blockIdx.x * blockDim.x + threadIdx.x;
    if (i < AHq * AFq) g_Wctx[i] = __float2bfloat16(Wctx[i]);
    if (i < Bq * IEq) {
        int b = i >> 9, c = i & 511;
        g_x[(size_t)b * XK + c] = __uint_as_float(f2tf32(xt[i]));
    }
    if (i < Bq * RSq) {
        int b = i >> 9, c = i & 511;
        g_x[(size_t)b * XK + IEq + AFq + c] = __uint_as_float(f2tf32(h0[i]));
    }
}

// ---------------- K0b: build g_Wg = [Wih | Whh] tf32-rounded, rows n=0..2047, k=0..3071 ----------------
__global__ void k0b_wg(const float* __restrict__ Wih, const float* __restrict__ Whh) {
    int i = blockIdx.x * blockDim.x + threadIdx.x;   // over 2048*768 float4s
    if (i >= 4 * RSq * (XK / 4)) return;
    int n = i / (XK / 4), kq = i % (XK / 4);
    float4 v;
    if (kq < 640) v = *(const float4*)(Wih + (size_t)n * 2560 + kq * 4);
    else          v = *(const float4*)(Whh + (size_t)n * 512 + (kq - 640) * 4);
    uint4 o = make_uint4(f2tf32(v.x), f2tf32(v.y), f2tf32(v.z), f2tf32(v.w));
    ((uint4*)g_Wg)[(size_t)n * (XK / 4) + kq] = o;
}

// ---------------- K1: att_h = h0 @ W_h2a^T + b_h2a ----------------
__global__ void k1_atth(const float* __restrict__ h0, const float* __restrict__ W,
                        const float* __restrict__ bias) {
    __shared__ float As[16][16];
    __shared__ float Bs[16][17];
    int tx = threadIdx.x, ty = threadIdx.y;
    int b  = blockIdx.x * 16 + ty;
    int j  = blockIdx.y * 16 + tx;
    float acc = 0.f;
    for (int k0 = 0; k0 < RSq; k0 += 16) {
        As[ty][tx] = h0[b * RSq + k0 + tx];
        Bs[ty][tx] = W[(blockIdx.y * 16 + ty) * RSq + k0 + tx];
        __syncthreads();
        #pragma unroll
        for (int kk = 0; kk < 16; kk++) acc += As[ty][kk] * Bs[tx][kk];
        __syncthreads();
    }
    g_att_h[b * AHq + j] = acc + bias[j];
}

// ---------------- nop: keeps k2 at ncu capture slot ----------------
__global__ void k_nop() {}

// ---------------- K2: fused scores — bf16 smem both operands, 3-stage, 1 barrier/iter ----------------
// Grid (4, 392): nb fastest (A L2 reuse). Block 256 = 8 warps (2m x 4n). Tile 128x128xk32.
#define BROW 80                  // bf16 tile row stride (64B data + 16 pad)
#define TSTG (128 * BROW)        // 10240
#define OFF_B2  (3 * TSTG)                  // 30720
#define OFF_ADD (OFF_B2 + 3 * TSTG)         // 61440
#define OFF_WAL (OFF_ADD + 2 * 128 * 4)     // 62464
#define OFF_RED (OFF_WAL + 128 * 4)         // 62976
#define K2_SMEM (OFF_RED + 128 * 4 * 4)     // 65024
#define NKT2 (AFq / 32)          // 64

__global__ void __launch_bounds__(256, 2)
k2_scores(const float* __restrict__ att, const float* __restrict__ bctx,
          const float* __restrict__ Wal) {
    extern __shared__ __align__(16) char sm[];
    uint32_t smb = smem_u32(sm);
    float* s_add = (float*)(sm + OFF_ADD);
    float* s_wal = (float*)(sm + OFF_WAL);
    float* s_red = (float*)(sm + OFF_RED);

    int tid = threadIdx.x;
    int warp = tid >> 5, lane = tid & 31;
    int g = lane >> 2, t = lane & 3;
    int wm = warp >> 2, wn = warp & 3;
    int nb    = blockIdx.x;
    int mbase = blockIdx.y * 128;
    int nbase = nb * 128;
    int b0 = mbase / Lq;

    {
        int j = tid >> 7, nc = tid & 127;
        int bb = b0 + j; if (bb >= Bq) bb = Bq - 1;
        s_add[j * 128 + nc] = bctx[nbase + nc] + g_att_h[(size_t)bb * AHq + nbase + nc];
        if (tid < 128) s_wal[tid] = Wal[nbase + tid];
    }

    float acc[4][4][4];
    #pragma unroll
    for (int a = 0; a < 4; a++)
        #pragma unroll
        for (int b = 0; b < 4; b++)
            #pragma unroll
            for (int c = 0; c < 4; c++) acc[a][b][c] = 0.f;

    // precomputed per-thread staging addresses
    const float* aP[4];  uint32_t aOff[4];
    #pragma unroll
    for (int q = 0; q < 4; q++) {
        int idx = q * 256 + tid;
        int row = idx >> 3, seg = idx & 7;     // 128 rows x 8 segs of 8 bf16 (=4 f32 src each... 8B dst)
        aP[q]   = att + (size_t)(mbase + row) * AFq + seg * 4;
        aOff[q] = row * BROW + seg * 8;
    }
    const __nv_bfloat16* bP[2]; uint32_t bOff[2];
    #pragma unroll
    for (int q = 0; q < 2; q++) {
        int idx = q * 256 + tid;
        int row = idx >> 2, c = idx & 3;
        bP[q]   = g_Wctx + (size_t)(nbase + row) * AFq + c * 8;
        bOff[q] = row * BROW + c * 16;
    }

    uint2 regA[4];
    auto ldgA = [&](int kt) {
        int k0 = kt * 32;
        #pragma unroll
        for (int q = 0; q < 4; q++) {
            float4 v = *(const float4*)(aP[q] + k0);
            regA[q] = make_uint2(packbf(v.x, v.y), packbf(v.z, v.w));
        }
    };
    auto stsA = [&](int s) {
        uint32_t base = smb + s * TSTG;
        #pragma unroll
        for (int q = 0; q < 4; q++)
            asm volatile("st.shared.v2.b32 [%0], {%1, %2};"
                :: "r"(base + aOff[q]), "r"(regA[q].x), "r"(regA[q].y) : "memory");
    };
    auto cpB = [&](int kt, int s) {
        int k0 = kt * 32;
        uint32_t base = smb + OFF_B2 + s * TSTG;
        #pragma unroll
        for (int q = 0; q < 2; q++)
            cp_async16(base + bOff[q], bP[q] + k0);
    };

    // ldmatrix fragment addresses (R7-proven mappings)
    uint32_t a_off = (uint32_t)(wm * 64 + (lane & 15)) * BROW + ((lane & 16) ? 16 : 0);
    uint32_t b_off = (uint32_t)(wn * 32 + ((lane >> 4) & 1) * 8 + (lane & 7)) * BROW +
                     ((lane >> 3) & 1) * 16;

    ldgA(0);
    cpB(0, 0); cp_commit();
    cpB(1, 1); cp_commit();

    for (int kt = 0; kt < NKT2; kt++) {
        int s = kt % 3;
        stsA(s);
        cp_wait1();
        __syncthreads();
        if (kt < NKT2 - 1) ldgA(kt + 1);
        if (kt < NKT2 - 2) cpB(kt + 2, (kt + 2) % 3);
        cp_commit();

        uint32_t aBase = smb + s * TSTG + a_off;
        uint32_t bBase = smb + OFF_B2 + s * TSTG + b_off;
        #pragma unroll
        for (int k16 = 0; k16 < 2; k16++) {
            uint32_t bfr[4][2];
            ldsm_x4(bfr[0][0], bfr[0][1], bfr[1][0], bfr[1][1], bBase + k16 * 32);
            ldsm_x4(bfr[2][0], bfr[2][1], bfr[3][0], bfr[3][1], bBase + 16 * BROW + k16 * 32);
            #pragma unroll
            for (int mf = 0; mf < 4; mf++) {
                uint32_t afr[4];
                ldsm_x4(afr[0], afr[1], afr[2], afr[3],
                        aBase + (uint32_t)mf * 16 * BROW + k16 * 32);
                #pragma unroll
                for (int nf = 0; nf < 4; nf++)
                    mma_bf16(acc[mf][nf], afr, bfr[nf]);
            }
        }
        // no trailing barrier: 3-stage distance + top-of-iter barrier cover all hazards
    }

    // epilogue: partial score over this block's 128 columns
    float rs[4][2];
    #pragma unroll
    for (int mf = 0; mf < 4; mf++) {
        #pragma unroll
        for (int hh = 0; hh < 2; hh++) {
            int row_l = wm * 64 + mf * 16 + hh * 8 + g;
            int m = mbase + row_l;
            int jb = (m / Lq) - b0; if (jb > 1) jb = 1;
            const float* addp = s_add + jb * 128;
            float s = 0.f;
            #pragma unroll
            for (int nf = 0; nf < 4; nf++) {
                #pragma unroll
                for (int ci = 0; ci < 2; ci++) {
                    int nc = wn * 32 + nf * 8 + 2 * t + ci;
                    float v = acc[mf][nf][hh * 2 + ci] + addp[nc];
                    s += s_wal[nc] * tanhf(v);
                }
            }
            rs[mf][hh] = s;
        }
    }
    #pragma unroll
    for (int off = 1; off < 4; off <<= 1)
        #pragma unroll
        for (int mf = 0; mf < 4; mf++)
            #pragma unroll
            for (int hh = 0; hh < 2; hh++)
                rs[mf][hh] += __shfl_xor_sync(0xffffffffu, rs[mf][hh], off);
    __syncthreads();   // accs done everywhere before reusing smem
    if (t == 0) {
        #pragma unroll
        for (int mf = 0; mf < 4; mf++)
            #pragma unroll
            for (int hh = 0; hh < 2; hh++)
                s_red[(wm * 64 + mf * 16 + hh * 8 + g) * 4 + wn] = rs[mf][hh];
    }
    __syncthreads();
    if (tid < 128) {
        float s = s_red[tid * 4] + s_red[tid * 4 + 1] + s_red[tid * 4 + 2] + s_red[tid * 4 + 3];
        g_part[(size_t)nb * Mq + mbase + tid] = s;
    }
}

// ---------------- K3: sum partials + softmax over L=196 ----------------
__global__ void k3_softmax(const float* __restrict__ bal) {
    int b = blockIdx.x;
    int tid = threadIdx.x;
    __shared__ float sh[256];
    float v = -1e30f;
    if (tid < Lq) {
        int m = b * Lq + tid;
        v = g_part[m] + g_part[Mq + m] + g_part[2 * Mq + m] + g_part[3 * Mq + m] + bal[0];
    }
    sh[tid] = v; __syncthreads();
    for (int s = 128; s > 0; s >>= 1) {
        if (tid < s) sh[tid] = fmaxf(sh[tid], sh[tid + s]);
        __syncthreads();
    }
    float mx = sh[0]; __syncthreads();
    float e = (tid < Lq) ? __expf(v - mx) : 0.f;
    sh[tid] = e; __syncthreads();
    for (int s = 128; s > 0; s >>= 1) {
        if (tid < s) sh[tid] += sh[tid + s];
        __syncthreads();
    }
    float inv = 1.f / sh[0];
    if (tid < Lq) g_weight[b * Lq + tid] = e * inv;
}

// ---------------- K4: att_res = weight @ att_feats (tf32-rounded into g_x) ----------------
__global__ void k4_attres(const float* __restrict__ att) {
    int b  = blockIdx.y;
    int a0 = blockIdx.x * 1024 + threadIdx.x * 4;
    __shared__ float w[Lq];
    for (int i = threadIdx.x; i < Lq; i += blockDim.x) w[i] = g_weight[b * Lq + i];
    __syncthreads();
    float4 acc = make_float4(0.f, 0.f, 0.f, 0.f);
    const float* base = att + (size_t)b * Lq * AFq + a0;
    #pragma unroll 4
    for (int l = 0; l < Lq; l++) {
        float4 v = *(const float4*)(base + (size_t)l * AFq);
        float wl = w[l];
        acc.x += wl * v.x; acc.y += wl * v.y; acc.z += wl * v.z; acc.w += wl * v.w;
    }
    acc.x = __uint_as_float(f2tf32(acc.x));
    acc.y = __uint_as_float(f2tf32(acc.y));
    acc.z = __uint_as_float(f2tf32(acc.z));
    acc.w = __uint_as_float(f2tf32(acc.w));
    *(float4*)(g_x + (size_t)b * XK + IEq + a0) = acc;
}

// ---------------- K5: gate GEMM, tf32, cp.async tiled, split-K=3 ----------------
// Grid (2, 16, 3). Block 256 = 8 warps (2m x 4n). Tile 128x128, K-seg 1024, chunk 32.
#define R5 144                   // f32 tile row stride (36 words: conflict-free 4g+t)
#define S5 (128 * R5)            // 18432
#define K5_SMEM (6 * S5)         // 110592
__global__ void __launch_bounds__(256, 1)
k5_gates() {
    extern __shared__ __align__(16) char sm5[];
    uint32_t smb = smem_u32(sm5);
    int tid = threadIdx.x;
    int warp = tid >> 5, lane = tid & 31;
    int g = lane >> 2, t = lane & 3;
    int wm = warp >> 2, wn = warp & 3;
    int mbase = blockIdx.x * 128;
    int nbase = blockIdx.y * 128;
    int kb    = blockIdx.z * 1024;

    float acc[4][4][4];
    #pragma unroll
    for (int a = 0; a < 4; a++)
        #pragma unroll
        for (int b = 0; b < 4; b++)
            #pragma unroll
            for (int c = 0; c < 4; c++) acc[a][b][c] = 0.f;

    const float* aP[4]; const float* bP[4]; uint32_t tOff[4];
    #pragma unroll
    for (int q = 0; q < 4; q++) {
        int idx = q * 256 + tid;
        int row = idx >> 3, seg = idx & 7;
        aP[q] = g_x  + (size_t)(mbase + row) * XK + kb + seg * 4;
        bP[q] = g_Wg + (size_t)(nbase + row) * XK + kb + seg * 4;
        tOff[q] = row * R5 + seg * 16;
    }
    auto issue = [&](int kt, int s) {
        int k0 = kt * 32;
        uint32_t aD = smb + s * S5;
        uint32_t bD = smb + 3 * S5 + s * S5;
        #pragma unroll
        for (int q = 0; q < 4; q++) {
            cp_async16(aD + tOff[q], aP[q] + k0);
            cp_async16(bD + tOff[q], bP[q] + k0);
        }
    };

    issue(0, 0); cp_commit();
    issue(1, 1); cp_commit();

    uint32_t aFr = (uint32_t)(wm * 64 + g) * R5 + t * 4;
    uint32_t bFr = (uint32_t)(wn * 32 + g) * R5 + t * 4;

    for (int kt = 0; kt < 32; kt++) {
        int s = kt % 3;
        cp_wait1();
        __syncthreads();
        if (kt < 30) issue(kt + 2, (kt + 2) % 3);
        cp_commit();

        const char* aB = sm5 + s * S5;
        const char* bB = sm5 + 3 * S5 + s * S5;
        #pragma unroll
        for (int ks = 0; ks < 4; ks++) {
            uint32_t kc = ks * 32;   // 8 floats
            uint32_t bfr[4][2];
            #pragma unroll
            for (int nf = 0; nf < 4; nf++) {
                bfr[nf][0] = *(const uint32_t*)(bB + bFr + nf * 8 * R5 + kc);
                bfr[nf][1] = *(const uint32_t*)(bB + bFr + nf * 8 * R5 + kc + 16);
            }
            #pragma unroll
            for (int mf = 0; mf < 4; mf++) {
                uint32_t afr[4];
                afr[0] = *(const uint32_t*)(aB + aFr + mf * 16 * R5 + kc);
                afr[1] = *(const uint32_t*)(aB + aFr + (mf * 16 + 8) * R5 + kc);
                afr[2] = *(const uint32_t*)(aB + aFr + mf * 16 * R5 + kc + 16);
                afr[3] = *(const uint32_t*)(aB + aFr + (mf * 16 + 8) * R5 + kc + 16);
                #pragma unroll
                for (int nf = 0; nf < 4; nf++)
                    mma_tf32(acc[mf][nf], afr, bfr[nf]);
            }
        }
    }

    float* outp = g_gpart + (size_t)blockIdx.z * GSEG;
    #pragma unroll
    for (int mf = 0; mf < 4; mf++)
        #pragma unroll
        for (int nf = 0; nf < 4; nf++)
            #pragma unroll
            for (int idx = 0; idx < 4; idx++) {
                int hh = idx >> 1, ci = idx & 1;
                int row = mbase + wm * 64 + mf * 16 + hh * 8 + g;
                int col = nbase + wn * 32 + nf * 8 + 2 * t + ci;
                outp[(size_t)row * 2048 + col] = acc[mf][nf][idx];
            }
}

// ---------------- K6: sum split-K partials + LSTM pointwise + output ----------------
__global__ void k6_lstm(const float* __restrict__ c0, float* __restrict__ out, int out_size) {
    int i = blockIdx.x * blockDim.x + threadIdx.x;
    if (i >= Bq * RSq) return;
    int b = i >> 9, r = i & 511;
    size_t base = (size_t)b * 2048;
    auto gv = [&](int col) {
        size_t idx = base + col;
        return g_gpart[idx] + g_gpart[GSEG + idx] + g_gpart[2 * (size_t)GSEG + idx];
    };
    float gi = 1.f / (1.f + __expf(-gv(r)));
    float gf = 1.f / (1.f + __expf(-gv(512 + r)));
    float gg = tanhf(gv(1024 + r));
    float go = 1.f / (1.f + __expf(-gv(1536 + r)));
    float c = gf * c0[i] + gi * gg;
    float h = go * tanhf(c);
    const int N = Bq * RSq;
    out[i] = h;
    if (out_size >= 3 * N) { out[N + i] = h; out[2 * N + i] = c; }
    else if (out_size >= 2 * N) { out[N + i] = c; }
}

// ---------------- launch ----------------
extern "C" void kernel_launch(void* const* d_in, const int* in_sizes, int n_in,
                              void* d_out, int out_size) {
    const float* xt   = (const float*)d_in[0];
    const float* att  = (const float*)d_in[2];
    const float* h0   = (const float*)d_in[3];
    const float* c0   = (const float*)d_in[4];
    const float* Wctx = (const float*)d_in[5];
    const float* bctx = (const float*)d_in[6];
    const float* Wh2a = (const float*)d_in[7];
    const float* bh2a = (const float*)d_in[8];
    const float* Wal  = (const float*)d_in[9];
    const float* bal  = (const float*)d_in[10];
    const float* Wih  = (const float*)d_in[11];
    const float* Whh  = (const float*)d_in[12];
    float* out = (float*)d_out;

    static int attr_set = 0;
    if (!attr_set) {
        cudaFuncSetAttribute(k2_scores, cudaFuncAttributeMaxDynamicSharedMemorySize, K2_SMEM);
        cudaFuncSetAttribute(k5_gates,  cudaFuncAttributeMaxDynamicSharedMemorySize, K5_SMEM);
        attr_set = 1;
    }

    k0_prep<<<4096, 256>>>(Wctx, xt, h0);
    k1_atth<<<dim3(16, 32), dim3(16, 16)>>>(h0, Wh2a, bh2a);
    k_nop<<<1, 32>>>();
    k2_scores<<<dim3(4, Mq / 128), 256, K2_SMEM>>>(att, bctx, Wal);   // capture slot 3
    k3_softmax<<<Bq, 256>>>(bal);
    k0b_wg<<<6144, 256>>>(Wih, Whh);
    k4_attres<<<dim3(2, Bq), 256>>>(att);
    k5_gates<<<dim3(2, 16, 3), 256, K5_SMEM>>>();
    k6_lstm<<<(Bq * RSq + 255) / 256, 256>>>(c0, out, out_size);
}